// round 4
// baseline (speedup 1.0000x reference)
#include <cuda_runtime.h>

#define NN 50000
#define NE 800000
#define NG 256
#define FIN 256
#define HD 64

__device__ float g_q[NN * HD];
__device__ float g_k[NN * HD];
__device__ float g_v[NN * HD];
__device__ float g_vw[NN * HD];
__device__ float g_ex[NE];
__device__ float g_den[NG];

// ---------------------------------------------------------------------------
// QKV projection GEMM with packed fma.rn.f32x2 and double-buffered smem.
// out[N,64] = x[N,256] @ W[256,64] + b ; blockIdx.y selects {Q,K,V}.
// BM=128, BN=64, BK=16, 128 threads, 8x8 register tile per thread.
// Block (0,0) also zeroes the per-graph denominator bins (pass1 runs after).
// ---------------------------------------------------------------------------
__global__ __launch_bounds__(128) void qkv_gemm(
    const float* __restrict__ x,
    const float* __restrict__ Wq, const float* __restrict__ bq,
    const float* __restrict__ Wk, const float* __restrict__ bk,
    const float* __restrict__ Wv, const float* __restrict__ bv)
{
    __shared__ __align__(16) float xs[2][16][132];  // [buf][k][row]
    __shared__ __align__(16) float ws[2][16][64];   // [buf][k][col]

    if (blockIdx.x == 0 && blockIdx.y == 0) {
        g_den[threadIdx.x * 2]     = 0.f;
        g_den[threadIdx.x * 2 + 1] = 0.f;
    }

    const float* W; const float* bias; float* out;
    if (blockIdx.y == 0)      { W = Wq; bias = bq; out = g_q; }
    else if (blockIdx.y == 1) { W = Wk; bias = bk; out = g_k; }
    else                      { W = Wv; bias = bv; out = g_v; }

    const int tid = threadIdx.x;
    const int tx = tid & 7;         // col group: 8 cols
    const int ty = tid >> 3;        // row group: 8 rows
    const int row0 = blockIdx.x * 128;

    // Per-thread load coordinates (fixed across tiles).
    const int xr  = tid >> 2;            // base row for x loads (plus l*32)
    const int xkp = tid & 3;             // k-packet within tile
    const int wr  = tid >> 4;            // W row (plus l*8)
    const int wc4 = tid & 15;            // W col group

    unsigned long long acc[8][4];
#pragma unroll
    for (int i = 0; i < 8; i++)
#pragma unroll
        for (int j = 0; j < 4; j++) acc[i][j] = 0ull;

    float4 xv[4], wv[2];

    // Prologue: load tile 0.
#pragma unroll
    for (int l = 0; l < 4; l++) {
        int grow = row0 + xr + l * 32;
        xv[l] = make_float4(0.f, 0.f, 0.f, 0.f);
        if (grow < NN)
            xv[l] = *(const float4*)&x[(size_t)grow * FIN + xkp * 4];
    }
#pragma unroll
    for (int l = 0; l < 2; l++)
        wv[l] = *(const float4*)&W[(size_t)(wr + l * 8) * HD + wc4 * 4];

#pragma unroll
    for (int l = 0; l < 4; l++) {
        int r = xr + l * 32;
        xs[0][xkp * 4 + 0][r] = xv[l].x;
        xs[0][xkp * 4 + 1][r] = xv[l].y;
        xs[0][xkp * 4 + 2][r] = xv[l].z;
        xs[0][xkp * 4 + 3][r] = xv[l].w;
    }
#pragma unroll
    for (int l = 0; l < 2; l++)
        *(float4*)&ws[0][wr + l * 8][wc4 * 4] = wv[l];
    __syncthreads();

    for (int t = 0; t < FIN / 16; t++) {
        const int cur = t & 1;
        const int k0n = (t + 1) * 16;

        // Prefetch next tile into registers (latency hidden by compute).
        if (t < FIN / 16 - 1) {
#pragma unroll
            for (int l = 0; l < 4; l++) {
                int grow = row0 + xr + l * 32;
                xv[l] = make_float4(0.f, 0.f, 0.f, 0.f);
                if (grow < NN)
                    xv[l] = *(const float4*)&x[(size_t)grow * FIN + k0n + xkp * 4];
            }
#pragma unroll
            for (int l = 0; l < 2; l++)
                wv[l] = *(const float4*)&W[(size_t)(k0n + wr + l * 8) * HD + wc4 * 4];
        }

#pragma unroll
        for (int kk = 0; kk < 16; kk++) {
            float4 a0 = *(const float4*)&xs[cur][kk][ty * 8];
            float4 a1 = *(const float4*)&xs[cur][kk][ty * 8 + 4];
            float4 b0 = *(const float4*)&ws[cur][kk][tx * 8];
            float4 b1 = *(const float4*)&ws[cur][kk][tx * 8 + 4];
            unsigned long long bp[4];
            asm("mov.b64 %0, {%1, %2};" : "=l"(bp[0]) : "f"(b0.x), "f"(b0.y));
            asm("mov.b64 %0, {%1, %2};" : "=l"(bp[1]) : "f"(b0.z), "f"(b0.w));
            asm("mov.b64 %0, {%1, %2};" : "=l"(bp[2]) : "f"(b1.x), "f"(b1.y));
            asm("mov.b64 %0, {%1, %2};" : "=l"(bp[3]) : "f"(b1.z), "f"(b1.w));
            float av[8] = {a0.x, a0.y, a0.z, a0.w, a1.x, a1.y, a1.z, a1.w};
#pragma unroll
            for (int i = 0; i < 8; i++) {
                unsigned long long ad;
                asm("mov.b64 %0, {%1, %1};" : "=l"(ad) : "f"(av[i]));
#pragma unroll
                for (int j = 0; j < 4; j++)
                    asm("fma.rn.f32x2 %0, %1, %2, %0;"
                        : "+l"(acc[i][j]) : "l"(ad), "l"(bp[j]));
            }
        }

        if (t < FIN / 16 - 1) {
            const int nxt = cur ^ 1;
#pragma unroll
            for (int l = 0; l < 4; l++) {
                int r = xr + l * 32;
                xs[nxt][xkp * 4 + 0][r] = xv[l].x;
                xs[nxt][xkp * 4 + 1][r] = xv[l].y;
                xs[nxt][xkp * 4 + 2][r] = xv[l].z;
                xs[nxt][xkp * 4 + 3][r] = xv[l].w;
            }
#pragma unroll
            for (int l = 0; l < 2; l++)
                *(float4*)&ws[nxt][wr + l * 8][wc4 * 4] = wv[l];
        }
        __syncthreads();
    }

    float4 bias0 = *(const float4*)&bias[tx * 8];
    float4 bias1 = *(const float4*)&bias[tx * 8 + 4];
#pragma unroll
    for (int i = 0; i < 8; i++) {
        int grow = row0 + ty * 8 + i;
        if (grow < NN) {
            float r[8];
#pragma unroll
            for (int j = 0; j < 4; j++)
                asm("mov.b64 {%0, %1}, %2;"
                    : "=f"(r[j * 2]), "=f"(r[j * 2 + 1]) : "l"(acc[i][j]));
            float4 o0 = make_float4(r[0] + bias0.x, r[1] + bias0.y,
                                    r[2] + bias0.z, r[3] + bias0.w);
            float4 o1 = make_float4(r[4] + bias1.x, r[5] + bias1.y,
                                    r[6] + bias1.z, r[7] + bias1.w);
            *(float4*)&out[(size_t)grow * HD + tx * 8]     = o0;
            *(float4*)&out[(size_t)grow * HD + tx * 8 + 4] = o1;
        }
    }
}

// ---------------------------------------------------------------------------
// Pass 1: ex[e] = exp(dot(k[src], q[dest]) / 8); per-graph denominator into
// shared bins, one global flush per block. 2 edges per warp (16 lanes each).
// ---------------------------------------------------------------------------
__global__ __launch_bounds__(512) void edge_pass1(
    const int* __restrict__ ei,
    const int* __restrict__ batch)
{
    __shared__ float sden[NG];
    const int tid = threadIdx.x;
    if (tid < NG) sden[tid] = 0.f;
    __syncthreads();

    const int lane = tid & 31;
    const int half = lane >> 4;
    const int hl   = lane & 15;
    const int w = blockIdx.x * 16 + (tid >> 5);
    const int stride = gridDim.x * 16 * 2;

    for (int e = w * 2 + half; e < NE; e += stride) {
        int s = __ldg(&ei[e]);
        int d = __ldg(&ei[NE + e]);
        float4 kk = *(const float4*)&g_k[s * HD + hl * 4];
        float4 qq = *(const float4*)&g_q[d * HD + hl * 4];
        float p = kk.x * qq.x + kk.y * qq.y + kk.z * qq.z + kk.w * qq.w;
#pragma unroll
        for (int o = 8; o > 0; o >>= 1)
            p += __shfl_xor_sync(0xffffffffu, p, o);
        if (hl == 0) {
            float ex = __expf(p * 0.125f);
            g_ex[e] = ex;
            atomicAdd(&sden[__ldg(&batch[s])], ex);
        }
    }
    __syncthreads();
    if (tid < NG) {
        float v = sden[tid];
        if (v != 0.f) atomicAdd(&g_den[tid], v);
    }
}

// ---------------------------------------------------------------------------
// Node-wise normalization fold: vw[n] = v[n] * rcp(den[batch[n]] + 1e-6).
// One float4 per thread.
// ---------------------------------------------------------------------------
__global__ __launch_bounds__(256) void scale_v(const int* __restrict__ batch)
{
    int i = blockIdx.x * 256 + threadIdx.x;       // float4 index
    if (i >= NN * (HD / 4)) return;
    int node = i >> 4;
    float inv = __frcp_rn(g_den[__ldg(&batch[node])] + 1e-6f);
    float4 v = *(const float4*)&g_v[i * 4];
    v.x *= inv; v.y *= inv; v.z *= inv; v.w *= inv;
    *(float4*)&g_vw[i * 4] = v;
}

// ---------------------------------------------------------------------------
// Pass 2: out[dest] += vw[src] * ex[e].
// 2 edges per warp, 16 lanes x float4 each, red.global.add.v4.f32.
// ---------------------------------------------------------------------------
__global__ __launch_bounds__(256) void edge_pass2(
    const int* __restrict__ ei,
    float* __restrict__ out)
{
    const int lane = threadIdx.x & 31;
    const int half = lane >> 4;
    const int hl   = lane & 15;
    const int e = (blockIdx.x * 8 + (threadIdx.x >> 5)) * 2 + half;
    if (e >= NE) return;

    int s = __ldg(&ei[e]);
    int d = __ldg(&ei[NE + e]);

    float a = 0.f;
    if (hl == 0) a = g_ex[e];
    a = __shfl_sync(0xffffffffu, a, half << 4);

    float4 vv = *(const float4*)&g_vw[s * HD + hl * 4];
    float* dst = &out[d * HD + hl * 4];
    asm volatile("red.global.add.v4.f32 [%0], {%1, %2, %3, %4};"
                 :: "l"(dst), "f"(vv.x * a), "f"(vv.y * a),
                    "f"(vv.z * a), "f"(vv.w * a)
                 : "memory");
}

// ---------------------------------------------------------------------------
extern "C" void kernel_launch(void* const* d_in, const int* in_sizes, int n_in,
                              void* d_out, int out_size)
{
    const float* x     = (const float*)d_in[0];
    const float* Wq    = (const float*)d_in[1];
    const float* bq    = (const float*)d_in[2];
    const float* Wk    = (const float*)d_in[3];
    const float* bk    = (const float*)d_in[4];
    const float* Wv    = (const float*)d_in[5];
    const float* bv    = (const float*)d_in[6];
    const int*   ei    = (const int*)d_in[7];    // int32 (JAX x64 disabled)
    const int*   batch = (const int*)d_in[8];
    float* out = (float*)d_out;

    cudaMemsetAsync(d_out, 0, (size_t)out_size * sizeof(float));

    dim3 g((NN + 127) / 128, 3);
    qkv_gemm<<<g, 128>>>(x, Wq, bq, Wk, bk, Wv, bv);   // also zeroes g_den

    edge_pass1<<<296, 512>>>(ei, batch);
    scale_v<<<(NN * (HD / 4) + 255) / 256, 256>>>(batch);
    edge_pass2<<<NE / 16, 256>>>(ei, out);
}

// round 6
// speedup vs baseline: 1.2421x; 1.2421x over previous
#include <cuda_runtime.h>
#include <cuda_bf16.h>
#include <cstdint>

#define NN 50000
#define NE 800000
#define NG 256
#define FIN 256
#define HD 64

__device__ float g_q[NN * HD];
__device__ float g_k[NN * HD];
__device__ float g_v[NN * HD];
__device__ float g_vw[NN * HD];
__device__ float g_ex[NE];
__device__ float g_den[NG];
// W transposed: [n=192][k=256], bf16 hi/lo split
__device__ __nv_bfloat16 g_wth[192 * 256];
__device__ __nv_bfloat16 g_wtl[192 * 256];

// smem layout (dynamic): A hi/lo [128][64] bf16, B hi/lo [192][64] bf16
#define SMA_HI 0
#define SMA_LO 16384
#define SMB_HI 32768
#define SMB_LO (32768 + 24576)
#define SM_TOT (32768 + 49152)   // 80 KB

__device__ __forceinline__ uint32_t smem_u32(const void* p) {
    uint32_t a;
    asm("{ .reg .u64 t; cvta.to.shared.u64 t, %1; cvt.u32.u64 %0, t; }"
        : "=r"(a) : "l"(p));
    return a;
}
// xor swizzle: conflict-free ldmatrix, 128B rows
__device__ __forceinline__ uint32_t swz(uint32_t row, uint32_t kb) {
    return (row * 128 + kb * 16) ^ ((row & 7) << 4);
}
__device__ __forceinline__ void ldsm_x4(uint32_t* r, uint32_t addr) {
    asm volatile("ldmatrix.sync.aligned.m8n8.x4.shared.b16 {%0,%1,%2,%3}, [%4];"
                 : "=r"(r[0]), "=r"(r[1]), "=r"(r[2]), "=r"(r[3]) : "r"(addr));
}
__device__ __forceinline__ void mma_bf16(float* c, const uint32_t* a,
                                         const uint32_t* b) {
    asm volatile(
        "mma.sync.aligned.m16n8k16.row.col.f32.bf16.bf16.f32 "
        "{%0,%1,%2,%3}, {%4,%5,%6,%7}, {%8,%9}, {%0,%1,%2,%3};"
        : "+f"(c[0]), "+f"(c[1]), "+f"(c[2]), "+f"(c[3])
        : "r"(a[0]), "r"(a[1]), "r"(a[2]), "r"(a[3]), "r"(b[0]), "r"(b[1]));
}
__device__ __forceinline__ uint32_t pack_bf2(float x, float y) {
    __nv_bfloat162 h = {__float2bfloat16(x), __float2bfloat16(y)};
    return *(uint32_t*)&h;
}

// ---------------------------------------------------------------------------
// W pre-transpose: Wt[n][k] hi/lo from Wsel[k][n]. n in [0,192), sel = n>>6.
// ---------------------------------------------------------------------------
__global__ __launch_bounds__(256) void wt_build(
    const float* __restrict__ Wq, const float* __restrict__ Wk,
    const float* __restrict__ Wv)
{
    int n = blockIdx.x;               // 0..191
    int k = threadIdx.x;              // 0..255
    const float* W = (n < 64) ? Wq : (n < 128 ? Wk : Wv);
    float w = W[(size_t)k * HD + (n & 63)];
    __nv_bfloat16 h = __float2bfloat16(w);
    __nv_bfloat16 l = __float2bfloat16(w - __bfloat162float(h));
    g_wth[n * FIN + k] = h;
    g_wtl[n * FIN + k] = l;
}

// ---------------------------------------------------------------------------
// Fused QKV GEMM on HMMA (mma.sync bf16x3): D[128,192] = x @ [Wq|Wk|Wv] + b.
// 8 warps: 4 M-warps x 2 N-warps; per warp 2 m-tiles x 12 n-tiles.
// K chunked by 64 (4 chunks). Block 0 also zeroes g_den.
// ---------------------------------------------------------------------------
__global__ __launch_bounds__(256) void qkv_gemm_hmma(
    const float* __restrict__ x,
    const float* __restrict__ bq, const float* __restrict__ bk,
    const float* __restrict__ bv)
{
    extern __shared__ char smem[];
    const uint32_t sb = smem_u32(smem);
    const int tid = threadIdx.x;
    const int wid = tid >> 5;
    const int lane = tid & 31;
    const int m_warp = wid & 3;
    const int n_warp = wid >> 2;
    const int row0 = blockIdx.x * 128;

    if (blockIdx.x == 0) g_den[tid] = 0.f;

    float acc[2][12][4];
#pragma unroll
    for (int i = 0; i < 2; i++)
#pragma unroll
        for (int j = 0; j < 12; j++)
#pragma unroll
            for (int t = 0; t < 4; t++) acc[i][j][t] = 0.f;

    // ldmatrix per-lane coordinates
    const int lm_r = lane & 15;       // row within 16-row group
    const int lm_h = lane >> 4;       // kblock half

    for (int c = 0; c < 4; c++) {
        __syncthreads();
        // ---- stage A: x[row0:+128, c*64:+64] -> bf16 hi/lo swizzled ----
#pragma unroll
        for (int it = 0; it < 4; it++) {
            int idx = tid + it * 256;         // 1024 (row,kb) pairs
            int r  = idx >> 3;
            int kb = idx & 7;
            int grow = row0 + r;
            float4 f0 = make_float4(0.f, 0.f, 0.f, 0.f), f1 = f0;
            if (grow < NN) {
                const float* src = &x[(size_t)grow * FIN + c * 64 + kb * 8];
                f0 = *(const float4*)src;
                f1 = *(const float4*)(src + 4);
            }
            float fv[8] = {f0.x, f0.y, f0.z, f0.w, f1.x, f1.y, f1.z, f1.w};
            uint32_t hi[4], lo[4];
#pragma unroll
            for (int j = 0; j < 4; j++) {
                float a = fv[j * 2], b = fv[j * 2 + 1];
                __nv_bfloat16 ha = __float2bfloat16(a);
                __nv_bfloat16 hb = __float2bfloat16(b);
                hi[j] = pack_bf2(a, b);
                lo[j] = pack_bf2(a - __bfloat162float(ha),
                                 b - __bfloat162float(hb));
            }
            uint32_t off = swz(r, kb);
            *(uint4*)(smem + SMA_HI + off) = make_uint4(hi[0], hi[1], hi[2], hi[3]);
            *(uint4*)(smem + SMA_LO + off) = make_uint4(lo[0], lo[1], lo[2], lo[3]);
        }
        // ---- stage B: Wt[0:192, c*64:+64] hi/lo -> swizzled smem copy ----
#pragma unroll
        for (int it = 0; it < 6; it++) {
            int idx = tid + it * 256;         // 1536 (n,kb) pairs
            int n  = idx >> 3;
            int kb = idx & 7;
            uint32_t off = swz(n, kb);
            *(uint4*)(smem + SMB_HI + off) =
                *(const uint4*)&g_wth[n * FIN + c * 64 + kb * 8];
            *(uint4*)(smem + SMB_LO + off) =
                *(const uint4*)&g_wtl[n * FIN + c * 64 + kb * 8];
        }
        __syncthreads();

        // ---- compute: 4 k-steps of k16 ----
#pragma unroll
        for (int ks = 0; ks < 4; ks++) {
            uint32_t ah[2][4], al[2][4];
#pragma unroll
            for (int mt = 0; mt < 2; mt++) {
                int r = m_warp * 32 + mt * 16 + lm_r;
                uint32_t o = swz(r, ks * 2 + lm_h);
                ldsm_x4(ah[mt], sb + SMA_HI + o);
                ldsm_x4(al[mt], sb + SMA_LO + o);
            }
            uint32_t bh[12][2], bl[12][2];
#pragma unroll
            for (int p = 0; p < 6; p++) {     // pairs of n-tiles
                int n = n_warp * 96 + p * 16 + lm_r;
                uint32_t o = swz(n, ks * 2 + lm_h);
                uint32_t t[4];
                ldsm_x4(t, sb + SMB_HI + o);
                bh[p * 2][0] = t[0]; bh[p * 2 + 1][0] = t[1];
                bh[p * 2][1] = t[2]; bh[p * 2 + 1][1] = t[3];
                ldsm_x4(t, sb + SMB_LO + o);
                bl[p * 2][0] = t[0]; bl[p * 2 + 1][0] = t[1];
                bl[p * 2][1] = t[2]; bl[p * 2 + 1][1] = t[3];
            }
#pragma unroll
            for (int mt = 0; mt < 2; mt++)
#pragma unroll
                for (int nt = 0; nt < 12; nt++) {
                    mma_bf16(acc[mt][nt], ah[mt], bh[nt]);
                    mma_bf16(acc[mt][nt], ah[mt], bl[nt]);
                    mma_bf16(acc[mt][nt], al[mt], bh[nt]);
                }
        }
    }

    // ---- epilogue ----
    const float* biases[3] = {bq, bk, bv};
    float* outs[3] = {g_q, g_k, g_v};
    const int r0 = lane >> 2;
    const int cp = (lane & 3) * 2;
#pragma unroll
    for (int mt = 0; mt < 2; mt++) {
        int gr = row0 + m_warp * 32 + mt * 16 + r0;
#pragma unroll
        for (int nt = 0; nt < 12; nt++) {
            int col = n_warp * 96 + nt * 8 + cp;
            int sel = col >> 6;
            int ci  = col & 63;
            float b0 = biases[sel][ci], b1 = biases[sel][ci + 1];
            if (gr < NN) {
                float2 st = make_float2(acc[mt][nt][0] + b0, acc[mt][nt][1] + b1);
                *(float2*)&outs[sel][(size_t)gr * HD + ci] = st;
            }
            if (gr + 8 < NN) {
                float2 st = make_float2(acc[mt][nt][2] + b0, acc[mt][nt][3] + b1);
                *(float2*)&outs[sel][(size_t)(gr + 8) * HD + ci] = st;
            }
        }
    }
}

// ---------------------------------------------------------------------------
// Pass 1: ex[e] = exp(dot(k[src], q[dest]) / 8); denominator via shared bins.
// ---------------------------------------------------------------------------
__global__ __launch_bounds__(512) void edge_pass1(
    const int* __restrict__ ei, const int* __restrict__ batch)
{
    __shared__ float sden[NG];
    const int tid = threadIdx.x;
    if (tid < NG) sden[tid] = 0.f;
    __syncthreads();

    const int lane = tid & 31;
    const int half = lane >> 4;
    const int hl   = lane & 15;
    const int w = blockIdx.x * 16 + (tid >> 5);
    const int stride = gridDim.x * 16 * 2;

    for (int e = w * 2 + half; e < NE; e += stride) {
        int s = __ldg(&ei[e]);
        int d = __ldg(&ei[NE + e]);
        float4 kk = *(const float4*)&g_k[s * HD + hl * 4];
        float4 qq = *(const float4*)&g_q[d * HD + hl * 4];
        float p = kk.x * qq.x + kk.y * qq.y + kk.z * qq.z + kk.w * qq.w;
#pragma unroll
        for (int o = 8; o > 0; o >>= 1)
            p += __shfl_xor_sync(0xffffffffu, p, o);
        if (hl == 0) {
            float ex = __expf(p * 0.125f);
            g_ex[e] = ex;
            atomicAdd(&sden[__ldg(&batch[s])], ex);
        }
    }
    __syncthreads();
    if (tid < NG) {
        float v = sden[tid];
        if (v != 0.f) atomicAdd(&g_den[tid], v);
    }
}

// ---------------------------------------------------------------------------
__global__ __launch_bounds__(256) void scale_v(const int* __restrict__ batch)
{
    int i = blockIdx.x * 256 + threadIdx.x;
    if (i >= NN * (HD / 4)) return;
    int node = i >> 4;
    float inv = __frcp_rn(g_den[__ldg(&batch[node])] + 1e-6f);
    float4 v = *(const float4*)&g_v[i * 4];
    v.x *= inv; v.y *= inv; v.z *= inv; v.w *= inv;
    *(float4*)&g_vw[i * 4] = v;
}

// ---------------------------------------------------------------------------
__global__ __launch_bounds__(256) void edge_pass2(
    const int* __restrict__ ei, float* __restrict__ out)
{
    const int lane = threadIdx.x & 31;
    const int half = lane >> 4;
    const int hl   = lane & 15;
    const int e = (blockIdx.x * 8 + (threadIdx.x >> 5)) * 2 + half;
    if (e >= NE) return;

    int s = __ldg(&ei[e]);
    int d = __ldg(&ei[NE + e]);

    float a = 0.f;
    if (hl == 0) a = g_ex[e];
    a = __shfl_sync(0xffffffffu, a, half << 4);

    float4 vv = *(const float4*)&g_vw[s * HD + hl * 4];
    float* dst = &out[d * HD + hl * 4];
    asm volatile("red.global.add.v4.f32 [%0], {%1, %2, %3, %4};"
                 :: "l"(dst), "f"(vv.x * a), "f"(vv.y * a),
                    "f"(vv.z * a), "f"(vv.w * a)
                 : "memory");
}

// ---------------------------------------------------------------------------
extern "C" void kernel_launch(void* const* d_in, const int* in_sizes, int n_in,
                              void* d_out, int out_size)
{
    const float* x     = (const float*)d_in[0];
    const float* Wq    = (const float*)d_in[1];
    const float* bq    = (const float*)d_in[2];
    const float* Wk    = (const float*)d_in[3];
    const float* bk    = (const float*)d_in[4];
    const float* Wv    = (const float*)d_in[5];
    const float* bv    = (const float*)d_in[6];
    const int*   ei    = (const int*)d_in[7];    // int32 (JAX x64 disabled)
    const int*   batch = (const int*)d_in[8];
    float* out = (float*)d_out;

    cudaFuncSetAttribute(qkv_gemm_hmma,
                         cudaFuncAttributeMaxDynamicSharedMemorySize, SM_TOT);

    cudaMemsetAsync(d_out, 0, (size_t)out_size * sizeof(float));

    wt_build<<<192, 256>>>(Wq, Wk, Wv);
    qkv_gemm_hmma<<<(NN + 127) / 128, 256, SM_TOT>>>(x, bq, bk, bv);

    edge_pass1<<<296, 512>>>(ei, batch);
    scale_v<<<(NN * (HD / 4) + 255) / 256, 256>>>(batch);
    edge_pass2<<<NE / 16, 256>>>(ei, out);
}